// round 8
// baseline (speedup 1.0000x reference)
#include <cuda_runtime.h>
#include <stdint.h>

#define B_   4096
#define F_   1024
#define H_   256
#define C_   10
#define T_   24
#define RPB  4

// ---- fused transposed weights: [W1T | W2T | W3T] (device global) ----
__device__ __align__(16) float g_W[(F_ + 2 * H_) * H_];
#define W2B  ((size_t)F_ * H_ * 4)            // byte offset of W2T
#define W3B  ((size_t)(F_ + H_) * H_ * 4)     // byte offset of W3T

// ---- packed f32x2 helpers (Blackwell) ----
__device__ __forceinline__ unsigned long long pk2(float lo, float hi) {
    unsigned long long r;
    asm("mov.b64 %0, {%1, %2};" : "=l"(r) : "f"(lo), "f"(hi));
    return r;
}
__device__ __forceinline__ void upk2(unsigned long long v, float& lo, float& hi) {
    asm("mov.b64 {%0, %1}, %2;" : "=f"(lo), "=f"(hi) : "l"(v));
}
__device__ __forceinline__ void addx2(unsigned long long& a, unsigned long long b) {
    asm("add.rn.f32x2 %0, %1, %2;" : "=l"(a) : "l"(a), "l"(b));
}

// per-row-group barrier (64 threads, ids 1..RPB)
#define BARG() asm volatile("bar.sync %0, 64;" :: "r"(barid) : "memory")

// ============================================================
// Tiled transpose of W1/W2/W3 into the fused device global.
// ============================================================
__global__ void __launch_bounds__(256) transpose_all(
    const float* __restrict__ W1, const float* __restrict__ W2,
    const float* __restrict__ W3) {
    __shared__ float tile[32][33];
    const int zi = blockIdx.z;
    const float* src = (zi == 0) ? W1 : ((zi == 1) ? W2 : W3);
    float* dst = (zi == 0) ? g_W : ((zi == 1) ? g_W + F_ * H_ : g_W + (F_ + H_) * H_);
    const int C = (zi == 0) ? F_ : H_;
    const int R = H_;
    if ((int)(blockIdx.x * 32) >= C) return;

    const int x = blockIdx.x * 32 + threadIdx.x;
    const int y0 = blockIdx.y * 32;
#pragma unroll
    for (int dy = threadIdx.y; dy < 32; dy += 8)
        tile[dy][threadIdx.x] = src[(size_t)(y0 + dy) * C + x];
    __syncthreads();
    const int x2 = y0 + threadIdx.x;
#pragma unroll
    for (int dy = threadIdx.y; dy < 32; dy += 8)
        dst[(size_t)(blockIdx.x * 32 + dy) * R + x2] = tile[threadIdx.x][dy];
}

// ============================================================
// gather over prescaled byte offsets, 4 accumulator chains, unroll 4
// ============================================================
__device__ __forceinline__ void gatherN(const char* __restrict__ wb,
                                        const uint32_t* __restrict__ lst, int n,
                                        unsigned long long& a01, unsigned long long& a23,
                                        unsigned long long& b01, unsigned long long& b23) {
    int e = 0;
    for (; e + 4 <= n; e += 4) {
        uint4 o = *(const uint4*)(lst + e);
        ulonglong2 w0 = *(const ulonglong2*)(wb + o.x);
        ulonglong2 w1 = *(const ulonglong2*)(wb + o.y);
        ulonglong2 w2 = *(const ulonglong2*)(wb + o.z);
        ulonglong2 w3 = *(const ulonglong2*)(wb + o.w);
        addx2(a01, w0.x); addx2(a23, w0.y);
        addx2(b01, w1.x); addx2(b23, w1.y);
        addx2(a01, w2.x); addx2(a23, w2.y);
        addx2(b01, w3.x); addx2(b23, w3.y);
    }
    for (; e < n; e++) {
        ulonglong2 w = *(const ulonglong2*)(wb + lst[e]);
        addx2(a01, w.x); addx2(a23, w.y);
    }
}

// ============================================================
// Main fused kernel (R7 structure, register-trimmed for occ=5):
// encoder + SNN + folded linear readout; dead steps 22/23 elided.
// 256 threads = RPB(4) independent 64-thread row groups.
// ============================================================
__global__ void __launch_bounds__(256, 5)
snn_kernel(const float* __restrict__ x,
           const float* __restrict__ b1, const float* __restrict__ b2,
           const float* __restrict__ b3, const float* __restrict__ Wli,
           float* __restrict__ out) {
    __shared__ uint32_t s_bits[RPB][T_][32];                 // 12 KB
    __shared__ __align__(16) uint16_t s_l1[RPB][F_];         // 8 KB
    __shared__ __align__(16) uint32_t s_lh[2][RPB][2 * H_];  // 16 KB (z1 then z2 offsets)
    __shared__ int s_cntA[RPB];
    __shared__ int s_cnt1[2][RPB];
    __shared__ int s_cnt2[2][RPB];
    __shared__ float s_part[RPB][2][C_];

    const int tid = threadIdx.x;
    const int r = tid >> 6;
    const int g = tid & 63;
    const int lane = tid & 31;
    const int j0 = g * 4;
    const int barid = r + 1;
    const int row = blockIdx.x * RPB + r;
    const float* xrow = x + (size_t)row * F_;

    // ---- zero this row's bitmaps & counters ----
    for (int i = g; i < T_ * 32; i += 64) ((uint32_t*)s_bits[r])[i] = 0;
    if (g == 0) {
        s_cntA[r] = 0;
        s_cnt1[0][r] = 0; s_cnt1[1][r] = 0;
        s_cnt2[0][r] = 0; s_cnt2[1][r] = 0;
    }
    BARG();

    // ---- fused encoder -> scatter spikes into per-step bitmaps ----
    {
        const uint32_t mybit = 1u << (g & 31);
        const int wbase = g >> 5;
#pragma unroll 1
        for (int m0 = 0; m0 < 16; m0 += 4) {
            float xv[4], vv[4];
            uint32_t mk[4];
#pragma unroll
            for (int j = 0; j < 4; j++) {
                xv[j] = xrow[g + 64 * (m0 + j)];
                vv[j] = 0.0f; mk[j] = 0u;
            }
#pragma unroll
            for (int t = 0; t < T_; t++) {
#pragma unroll
                for (int j = 0; j < 4; j++) {
                    vv[j] = vv[j] + 0.1f * (xv[j] - vv[j]);
                    if (vv[j] > 1.0f) { mk[j] |= (1u << t); vv[j] = 0.0f; }
                }
            }
#pragma unroll
            for (int j = 0; j < 4; j++) {
                uint32_t m = mk[j];
                const int w = wbase + 2 * (m0 + j);
                while (m) {
                    int t = __ffs(m) - 1; m &= m - 1;
                    atomicOr(&s_bits[r][t][w], mybit);
                }
            }
        }
    }
    BARG();

    // ---- build encoder active list for t=0 ----
    if (g < 32) {
        uint32_t w = s_bits[r][0][g];
        while (w) {
            int b = __ffs(w) - 1; w &= w - 1;
            int p = atomicAdd(&s_cntA[r], 1);
            s_l1[r][p] = (uint16_t)((g << 5) | b);
        }
    }
    BARG();

    float v1[4] = {0,0,0,0}, i1[4] = {0,0,0,0};
    float v2[4] = {0,0,0,0}, i2[4] = {0,0,0,0};
    float v3[4] = {0,0,0,0}, i3[4] = {0,0,0,0};
    float q[4]  = {0,0,0,0};
    int zpack;                     // bits 0-3: z1, bits 4-7: z2

    // readout coefficients: coef_t = 0.9^(23-t) - 0.8^(23-t)
    float c9 = 1.0f, c8 = 1.0f;
#pragma unroll
    for (int i = 0; i < T_ - 1; i++) { c9 *= 0.9f; c8 *= 0.8f; }

    const char* Wb = (const char*)g_W + (size_t)j0 * 4;   // single base pointer

    int par = 0;

#pragma unroll 1
    for (int t = 0; t < T_ - 2; t++) {       // steps 22/23 gathers are dead
        // ================= phase 1: layer 1 =================
        {
            float4 bv = *(const float4*)(b1 + j0);
            unsigned long long a01 = pk2(bv.x, bv.y), a23 = pk2(bv.z, bv.w);
            unsigned long long b01 = pk2(0.f, 0.f),   b23 = pk2(0.f, 0.f);
            const uint16_t* lst = s_l1[r];
            const int n = s_cntA[r];
            int e = 0;
            for (; e + 4 <= n; e += 4) {
                ushort4 o = *(const ushort4*)(lst + e);
                ulonglong2 w0 = *(const ulonglong2*)(Wb + ((uint32_t)o.x << 10));
                ulonglong2 w1 = *(const ulonglong2*)(Wb + ((uint32_t)o.y << 10));
                ulonglong2 w2 = *(const ulonglong2*)(Wb + ((uint32_t)o.z << 10));
                ulonglong2 w3 = *(const ulonglong2*)(Wb + ((uint32_t)o.w << 10));
                addx2(a01, w0.x); addx2(a23, w0.y);
                addx2(b01, w1.x); addx2(b23, w1.y);
                addx2(a01, w2.x); addx2(a23, w2.y);
                addx2(b01, w3.x); addx2(b23, w3.y);
            }
            for (; e < n; e++) {
                ulonglong2 w = *(const ulonglong2*)(Wb + ((uint32_t)lst[e] << 10));
                addx2(a01, w.x); addx2(a23, w.y);
            }
            addx2(a01, b01); addx2(a23, b23);
            float a[4]; upk2(a01, a[0], a[1]); upk2(a23, a[2], a[3]);
            int* cnt = &s_cnt1[par][r];
            uint32_t* dl = s_lh[par][r];
            int zb = 0;
#pragma unroll
            for (int u = 0; u < 4; u++) {
                float vd = v1[u] + 0.1f * (i1[u] - v1[u]);
                i1[u] = i1[u] * 0.8f + a[u];
                bool z = vd > 0.23f;
                v1[u] = z ? 0.0f : vd;
                zb |= (z ? (1 << u) : 0);
                if (z) { int p = atomicAdd(cnt, 1); dl[p] = (uint32_t)((j0 + u) << 10); }
            }
            zpack = zb;
        }
        BARG();

        // ================= phase 2: layer 2 =================
        {
            if (g == 0) {       // untouched during phase 2
                s_cntA[r] = 0;
                s_cnt1[par ^ 1][r] = 0;
                s_cnt2[par ^ 1][r] = 0;
            }
            float4 bv = *(const float4*)(b2 + j0);
            unsigned long long a01 = pk2(bv.x, bv.y), a23 = pk2(bv.z, bv.w);
            unsigned long long b01 = pk2(0.f, 0.f),   b23 = pk2(0.f, 0.f);
            const int nA = s_cnt1[par][r];          // stable all phase
            gatherN(Wb + W2B, s_lh[par][r], nA, a01, a23, b01, b23);
            addx2(a01, b01); addx2(a23, b23);
            float a[4]; upk2(a01, a[0], a[1]); upk2(a23, a[2], a[3]);
            int* cnt = &s_cnt2[par][r];
            uint32_t* dl = s_lh[par][r];
            int zb = 0;
#pragma unroll
            for (int u = 0; u < 4; u++) {
                float vd = v2[u] + 0.1f * (i2[u] - v2[u]);
                i2[u] = i2[u] * 0.8f + a[u];
                bool z = vd > 0.23f;
                v2[u] = z ? 0.0f : vd;
                zb |= (z ? (1 << u) : 0);
                if (z) { int p = nA + atomicAdd(cnt, 1); dl[p] = (uint32_t)((j0 + u) << 10); }
            }
            zpack |= zb << 4;
        }
        BARG();

        // ===== phase 3: layer 3 (one combined gather) + readout fold + next enc list =====
        {
            float4 bv = *(const float4*)(b3 + j0);
            unsigned long long a01 = pk2(bv.x, bv.y), a23 = pk2(bv.z, bv.w);
            unsigned long long b01 = pk2(0.f, 0.f),   b23 = pk2(0.f, 0.f);
            const int n = s_cnt1[par][r] + s_cnt2[par][r];   // o2 = z1 + z2
            gatherN(Wb + W3B, s_lh[par][r], n, a01, a23, b01, b23);
            addx2(a01, b01); addx2(a23, b23);
            float a[4]; upk2(a01, a[0], a[1]); upk2(a23, a[2], a[3]);
            float coef = c9 - c8;
            c9 *= (1.0f / 0.9f);
            c8 *= 1.25f;
            const int zz = zpack;
#pragma unroll
            for (int u = 0; u < 4; u++) {
                float vd = v3[u] + 0.1f * (i3[u] - v3[u]);
                i3[u] = i3[u] * 0.8f + a[u];
                bool z = vd > 0.23f;
                v3[u] = z ? 0.0f : vd;
                float o3 = (z ? 1.0f : 0.0f)
                         + (float)((zz >> u) & 1) + (float)((zz >> (u + 4)) & 1);
                q[u] = fmaf(coef, o3, q[u]);
            }
            // build enc list for t+1 only while step t+1 still does real work
            if (t < T_ - 3 && g < 32) {
                uint32_t w = s_bits[r][t + 1][g];
                while (w) {
                    int b = __ffs(w) - 1; w &= w - 1;
                    int p = atomicAdd(&s_cntA[r], 1);
                    s_l1[r][p] = (uint16_t)((g << 5) | b);
                }
            }
        }
        BARG();
        par ^= 1;
    }

    // ===== step 22 epilogue: all gathers dead; spikes from local state only =====
    {
        float coef = c9 - c8;   // = 0.9 - 0.8 = 0.1
#pragma unroll
        for (int u = 0; u < 4; u++) {
            float vd1 = v1[u] + 0.1f * (i1[u] - v1[u]);
            float vd2 = v2[u] + 0.1f * (i2[u] - v2[u]);
            float vd3 = v3[u] + 0.1f * (i3[u] - v3[u]);
            float o3 = (vd1 > 0.23f ? 1.0f : 0.0f)
                     + (vd2 > 0.23f ? 1.0f : 0.0f)
                     + (vd3 > 0.23f ? 1.0f : 0.0f);
            q[u] = fmaf(coef, o3, q[u]);
        }
    }
    // step 23: output coefficient is exactly 0 -> nothing to do.

    // ---- final readout: out[b][c] = sum_k q_k * Wli[c][k] ----
    const int wig = (tid >> 5) & 1;
#pragma unroll
    for (int c = 0; c < C_; c++) {
        float4 w = *(const float4*)(Wli + c * H_ + j0);
        float s = q[0] * w.x + q[1] * w.y + q[2] * w.z + q[3] * w.w;
#pragma unroll
        for (int off = 16; off; off >>= 1)
            s += __shfl_xor_sync(0xffffffffu, s, off);
        if (lane == 0) s_part[r][wig][c] = s;
    }
    BARG();
    if (g < C_) out[(size_t)row * C_ + g] = s_part[r][0][g] + s_part[r][1][g];
}

// ============================================================
extern "C" void kernel_launch(void* const* d_in, const int* in_sizes, int n_in,
                              void* d_out, int out_size) {
    (void)in_sizes; (void)n_in; (void)out_size;
    const float* x   = (const float*)d_in[0];
    const float* W1  = (const float*)d_in[1];
    const float* b1  = (const float*)d_in[2];
    const float* W2  = (const float*)d_in[3];
    const float* b2  = (const float*)d_in[4];
    const float* W3  = (const float*)d_in[5];
    const float* b3  = (const float*)d_in[6];
    const float* Wli = (const float*)d_in[7];
    float* out = (float*)d_out;

    transpose_all<<<dim3(F_ / 32, H_ / 32, 3), dim3(32, 8)>>>(W1, W2, W3);
    snn_kernel<<<B_ / RPB, 256>>>(x, b1, b2, b3, Wli, out);
}

// round 9
// speedup vs baseline: 1.1877x; 1.1877x over previous
#include <cuda_runtime.h>
#include <stdint.h>

#define B_   4096
#define F_   1024
#define H_   256
#define C_   10
#define T_   24
#define RPB  4
#define NBLK (B_ / RPB)
#define GRID 608

// ---- transposed weights (device globals; no allocation) ----
__device__ __align__(16) float g_W1T[F_ * H_];   // [f][j]
__device__ __align__(16) float g_W2T[H_ * H_];   // [k][j]
__device__ __align__(16) float g_W3T[H_ * H_];   // [k][j]
__device__ int g_ctr;                            // work-stealing cursor

// ---- packed f32x2 helpers (Blackwell) ----
__device__ __forceinline__ unsigned long long pk2(float lo, float hi) {
    unsigned long long r;
    asm("mov.b64 %0, {%1, %2};" : "=l"(r) : "f"(lo), "f"(hi));
    return r;
}
__device__ __forceinline__ void upk2(unsigned long long v, float& lo, float& hi) {
    asm("mov.b64 {%0, %1}, %2;" : "=f"(lo), "=f"(hi) : "l"(v));
}
__device__ __forceinline__ void addx2(unsigned long long& a, unsigned long long b) {
    asm("add.rn.f32x2 %0, %1, %2;" : "=l"(a) : "l"(a), "l"(b));
}

// per-row-group barrier (64 threads, ids 1..RPB)
#define BARG() asm volatile("bar.sync %0, 64;" :: "r"(barid) : "memory")

// ============================================================
// Tiled transpose of W1/W2/W3; also resets the steal cursor.
// ============================================================
__global__ void __launch_bounds__(256) transpose_all(
    const float* __restrict__ W1, const float* __restrict__ W2,
    const float* __restrict__ W3) {
    __shared__ float tile[32][33];
    const int zi = blockIdx.z;
    if (zi == 0 && blockIdx.x == 0 && blockIdx.y == 0 &&
        threadIdx.x == 0 && threadIdx.y == 0)
        g_ctr = 0;
    const float* src = (zi == 0) ? W1 : ((zi == 1) ? W2 : W3);
    float* dst = (zi == 0) ? g_W1T : ((zi == 1) ? g_W2T : g_W3T);
    const int C = (zi == 0) ? F_ : H_;
    const int R = H_;
    if ((int)(blockIdx.x * 32) >= C) return;

    const int x = blockIdx.x * 32 + threadIdx.x;
    const int y0 = blockIdx.y * 32;
#pragma unroll
    for (int dy = threadIdx.y; dy < 32; dy += 8)
        tile[dy][threadIdx.x] = src[(size_t)(y0 + dy) * C + x];
    __syncthreads();
    const int x2 = y0 + threadIdx.x;
#pragma unroll
    for (int dy = threadIdx.y; dy < 32; dy += 8)
        dst[(size_t)(blockIdx.x * 32 + dy) * R + x2] = tile[threadIdx.x][dy];
}

// ============================================================
// gather over prescaled byte offsets, 4 accumulator chains, unroll 4
// ============================================================
__device__ __forceinline__ void gatherN(const char* __restrict__ wb,
                                        const uint32_t* __restrict__ lst, int n,
                                        unsigned long long& a01, unsigned long long& a23,
                                        unsigned long long& b01, unsigned long long& b23) {
    int e = 0;
    for (; e + 4 <= n; e += 4) {
        uint4 o = *(const uint4*)(lst + e);
        ulonglong2 w0 = *(const ulonglong2*)(wb + o.x);
        ulonglong2 w1 = *(const ulonglong2*)(wb + o.y);
        ulonglong2 w2 = *(const ulonglong2*)(wb + o.z);
        ulonglong2 w3 = *(const ulonglong2*)(wb + o.w);
        addx2(a01, w0.x); addx2(a23, w0.y);
        addx2(b01, w1.x); addx2(b23, w1.y);
        addx2(a01, w2.x); addx2(a23, w2.y);
        addx2(b01, w3.x); addx2(b23, w3.y);
    }
    for (; e < n; e++) {
        ulonglong2 w = *(const ulonglong2*)(wb + lst[e]);
        addx2(a01, w.x); addx2(a23, w.y);
    }
}

// ============================================================
// Persistent work-stealing SNN kernel (R7 body per block):
// encoder + SNN (dead steps 22/23 elided) + folded linear readout.
// Each CTA loops: steal a 4-row block, process it fully.
// ============================================================
__global__ void __launch_bounds__(256, 4)
snn_kernel(const float* __restrict__ x,
           const float* __restrict__ b1, const float* __restrict__ b2,
           const float* __restrict__ b3, const float* __restrict__ Wli,
           float* __restrict__ out) {
    __shared__ uint32_t s_bits[RPB][T_][32];                 // 12 KB
    __shared__ __align__(16) uint16_t s_l1[RPB][F_];         // 8 KB
    __shared__ __align__(16) uint32_t s_lh[2][RPB][2 * H_];  // 16 KB (z1 then z2 offsets)
    __shared__ int s_cntA[RPB];
    __shared__ int s_cnt1[2][RPB];
    __shared__ int s_cnt2[2][RPB];
    __shared__ float s_part[RPB][2][C_];
    __shared__ int s_blk;

    const int tid = threadIdx.x;
    const int r = tid >> 6;
    const int g = tid & 63;
    const int lane = tid & 31;
    const int j0 = g * 4;
    const int barid = r + 1;

    const char* W1b = (const char*)g_W1T + (size_t)j0 * 4;
    const char* W2b = (const char*)g_W2T + (size_t)j0 * 4;
    const char* W3b = (const char*)g_W3T + (size_t)j0 * 4;

    for (;;) {
        __syncthreads();                 // smem from previous block fully consumed
        if (tid == 0) s_blk = atomicAdd(&g_ctr, 1);
        __syncthreads();
        const int blk = s_blk;
        if (blk >= NBLK) break;

        const int row = blk * RPB + r;
        const float* xrow = x + (size_t)row * F_;

        // ---- zero this row's bitmaps & counters ----
        for (int i = g; i < T_ * 32; i += 64) ((uint32_t*)s_bits[r])[i] = 0;
        if (g == 0) {
            s_cntA[r] = 0;
            s_cnt1[0][r] = 0; s_cnt1[1][r] = 0;
            s_cnt2[0][r] = 0; s_cnt2[1][r] = 0;
        }
        BARG();

        // ---- fused encoder -> scatter spikes into per-step bitmaps ----
        {
            const uint32_t mybit = 1u << (g & 31);
            const int wbase = g >> 5;
#pragma unroll 1
            for (int m0 = 0; m0 < 16; m0 += 4) {
                float xv[4], vv[4];
                uint32_t mk[4];
#pragma unroll
                for (int j = 0; j < 4; j++) {
                    xv[j] = xrow[g + 64 * (m0 + j)];
                    vv[j] = 0.0f; mk[j] = 0u;
                }
#pragma unroll
                for (int t = 0; t < T_; t++) {
#pragma unroll
                    for (int j = 0; j < 4; j++) {
                        vv[j] = vv[j] + 0.1f * (xv[j] - vv[j]);
                        if (vv[j] > 1.0f) { mk[j] |= (1u << t); vv[j] = 0.0f; }
                    }
                }
#pragma unroll
                for (int j = 0; j < 4; j++) {
                    uint32_t m = mk[j];
                    const int w = wbase + 2 * (m0 + j);
                    while (m) {
                        int t = __ffs(m) - 1; m &= m - 1;
                        atomicOr(&s_bits[r][t][w], mybit);
                    }
                }
            }
        }
        BARG();

        // ---- build encoder active list for t=0 ----
        if (g < 32) {
            uint32_t w = s_bits[r][0][g];
            while (w) {
                int b = __ffs(w) - 1; w &= w - 1;
                int p = atomicAdd(&s_cntA[r], 1);
                s_l1[r][p] = (uint16_t)((g << 5) | b);
            }
        }
        BARG();

        float v1[4] = {0,0,0,0}, i1[4] = {0,0,0,0};
        float v2[4] = {0,0,0,0}, i2[4] = {0,0,0,0};
        float v3[4] = {0,0,0,0}, i3[4] = {0,0,0,0};
        float q[4]  = {0,0,0,0};
        float z1f[4], z2f[4];

        // readout coefficients: coef_t = 0.9^(23-t) - 0.8^(23-t)
        float c9 = 1.0f, c8 = 1.0f;
#pragma unroll
        for (int i = 0; i < T_ - 1; i++) { c9 *= 0.9f; c8 *= 0.8f; }

        int par = 0;

#pragma unroll 1
        for (int t = 0; t < T_ - 2; t++) {       // steps 22/23 gathers are dead
            // ================= phase 1: layer 1 =================
            {
                float4 bv = *(const float4*)(b1 + j0);
                unsigned long long a01 = pk2(bv.x, bv.y), a23 = pk2(bv.z, bv.w);
                unsigned long long b01 = pk2(0.f, 0.f),   b23 = pk2(0.f, 0.f);
                const uint16_t* lst = s_l1[r];
                const int n = s_cntA[r];
                int e = 0;
                for (; e + 4 <= n; e += 4) {
                    ushort4 o = *(const ushort4*)(lst + e);
                    ulonglong2 w0 = *(const ulonglong2*)(W1b + ((uint32_t)o.x << 10));
                    ulonglong2 w1 = *(const ulonglong2*)(W1b + ((uint32_t)o.y << 10));
                    ulonglong2 w2 = *(const ulonglong2*)(W1b + ((uint32_t)o.z << 10));
                    ulonglong2 w3 = *(const ulonglong2*)(W1b + ((uint32_t)o.w << 10));
                    addx2(a01, w0.x); addx2(a23, w0.y);
                    addx2(b01, w1.x); addx2(b23, w1.y);
                    addx2(a01, w2.x); addx2(a23, w2.y);
                    addx2(b01, w3.x); addx2(b23, w3.y);
                }
                for (; e < n; e++) {
                    ulonglong2 w = *(const ulonglong2*)(W1b + ((uint32_t)lst[e] << 10));
                    addx2(a01, w.x); addx2(a23, w.y);
                }
                addx2(a01, b01); addx2(a23, b23);
                float a[4]; upk2(a01, a[0], a[1]); upk2(a23, a[2], a[3]);
                int* cnt = &s_cnt1[par][r];
                uint32_t* dl = s_lh[par][r];
#pragma unroll
                for (int u = 0; u < 4; u++) {
                    float vd = v1[u] + 0.1f * (i1[u] - v1[u]);
                    i1[u] = i1[u] * 0.8f + a[u];
                    bool z = vd > 0.23f;
                    v1[u] = z ? 0.0f : vd;
                    z1f[u] = z ? 1.0f : 0.0f;
                    if (z) { int p = atomicAdd(cnt, 1); dl[p] = (uint32_t)((j0 + u) << 10); }
                }
            }
            BARG();

            // ================= phase 2: layer 2 =================
            {
                if (g == 0) {       // untouched during phase 2
                    s_cntA[r] = 0;
                    s_cnt1[par ^ 1][r] = 0;
                    s_cnt2[par ^ 1][r] = 0;
                }
                float4 bv = *(const float4*)(b2 + j0);
                unsigned long long a01 = pk2(bv.x, bv.y), a23 = pk2(bv.z, bv.w);
                unsigned long long b01 = pk2(0.f, 0.f),   b23 = pk2(0.f, 0.f);
                const int nA = s_cnt1[par][r];          // stable all phase
                gatherN(W2b, s_lh[par][r], nA, a01, a23, b01, b23);
                addx2(a01, b01); addx2(a23, b23);
                float a[4]; upk2(a01, a[0], a[1]); upk2(a23, a[2], a[3]);
                int* cnt = &s_cnt2[par][r];
                uint32_t* dl = s_lh[par][r];
#pragma unroll
                for (int u = 0; u < 4; u++) {
                    float vd = v2[u] + 0.1f * (i2[u] - v2[u]);
                    i2[u] = i2[u] * 0.8f + a[u];
                    bool z = vd > 0.23f;
                    v2[u] = z ? 0.0f : vd;
                    z2f[u] = z ? 1.0f : 0.0f;
                    if (z) { int p = nA + atomicAdd(cnt, 1); dl[p] = (uint32_t)((j0 + u) << 10); }
                }
            }
            BARG();

            // ===== phase 3: layer 3 + readout fold + next enc list =====
            {
                float4 bv = *(const float4*)(b3 + j0);
                unsigned long long a01 = pk2(bv.x, bv.y), a23 = pk2(bv.z, bv.w);
                unsigned long long b01 = pk2(0.f, 0.f),   b23 = pk2(0.f, 0.f);
                const int n = s_cnt1[par][r] + s_cnt2[par][r];   // o2 = z1 + z2
                gatherN(W3b, s_lh[par][r], n, a01, a23, b01, b23);
                addx2(a01, b01); addx2(a23, b23);
                float a[4]; upk2(a01, a[0], a[1]); upk2(a23, a[2], a[3]);
                float coef = c9 - c8;
                c9 *= (1.0f / 0.9f);
                c8 *= 1.25f;
#pragma unroll
                for (int u = 0; u < 4; u++) {
                    float vd = v3[u] + 0.1f * (i3[u] - v3[u]);
                    i3[u] = i3[u] * 0.8f + a[u];
                    bool z = vd > 0.23f;
                    v3[u] = z ? 0.0f : vd;
                    float o3 = (z ? 1.0f : 0.0f) + z1f[u] + z2f[u];
                    q[u] = fmaf(coef, o3, q[u]);
                }
                // build enc list for t+1 only while step t+1 still does real work
                if (t < T_ - 3 && g < 32) {
                    uint32_t w = s_bits[r][t + 1][g];
                    while (w) {
                        int b = __ffs(w) - 1; w &= w - 1;
                        int p = atomicAdd(&s_cntA[r], 1);
                        s_l1[r][p] = (uint16_t)((g << 5) | b);
                    }
                }
            }
            BARG();
            par ^= 1;
        }

        // ===== step 22 epilogue: gathers dead; spikes from local state only =====
        {
            float coef = c9 - c8;   // = 0.9 - 0.8 = 0.1
#pragma unroll
            for (int u = 0; u < 4; u++) {
                float vd1 = v1[u] + 0.1f * (i1[u] - v1[u]);
                float vd2 = v2[u] + 0.1f * (i2[u] - v2[u]);
                float vd3 = v3[u] + 0.1f * (i3[u] - v3[u]);
                float o3 = (vd1 > 0.23f ? 1.0f : 0.0f)
                         + (vd2 > 0.23f ? 1.0f : 0.0f)
                         + (vd3 > 0.23f ? 1.0f : 0.0f);
                q[u] = fmaf(coef, o3, q[u]);
            }
        }
        // step 23: output coefficient is exactly 0 -> nothing to do.

        // ---- final readout: out[b][c] = sum_k q_k * Wli[c][k] ----
        const int wig = (tid >> 5) & 1;
#pragma unroll
        for (int c = 0; c < C_; c++) {
            float4 w = *(const float4*)(Wli + c * H_ + j0);
            float s = q[0] * w.x + q[1] * w.y + q[2] * w.z + q[3] * w.w;
#pragma unroll
            for (int off = 16; off; off >>= 1)
                s += __shfl_xor_sync(0xffffffffu, s, off);
            if (lane == 0) s_part[r][wig][c] = s;
        }
        BARG();
        if (g < C_) out[(size_t)row * C_ + g] = s_part[r][0][g] + s_part[r][1][g];
    }
}

// ============================================================
extern "C" void kernel_launch(void* const* d_in, const int* in_sizes, int n_in,
                              void* d_out, int out_size) {
    (void)in_sizes; (void)n_in; (void)out_size;
    const float* x   = (const float*)d_in[0];
    const float* W1  = (const float*)d_in[1];
    const float* b1  = (const float*)d_in[2];
    const float* W2  = (const float*)d_in[3];
    const float* b2  = (const float*)d_in[4];
    const float* W3  = (const float*)d_in[5];
    const float* b3  = (const float*)d_in[6];
    const float* Wli = (const float*)d_in[7];
    float* out = (float*)d_out;

    transpose_all<<<dim3(F_ / 32, H_ / 32, 3), dim3(32, 8)>>>(W1, W2, W3);
    snn_kernel<<<GRID, 256>>>(x, b1, b2, b3, Wli, out);
}